// round 1
// baseline (speedup 1.0000x reference)
#include <cuda_runtime.h>

#define BB 2
#define HH 16
#define LL 2048
#define DD 64
#define NBH (BB*HH)
#define TQ 32
#define TK 64

// per-row 1/sum scratch (no cudaMalloc allowed)
__device__ float g_inv[NBH * LL];

__global__ __launch_bounds__(256) void attn_kernel(
    const float* __restrict__ q, const float* __restrict__ k,
    const float* __restrict__ v, const int* __restrict__ valid,
    const float* __restrict__ scale_p,
    float* __restrict__ res, float* __restrict__ attw)
{
    __shared__ float Qs[TQ][65];
    __shared__ float Ks[TK][65];   // reused for K tile then V tile
    __shared__ float Es[TQ][65];
    __shared__ float l_sh[TQ];
    __shared__ float inv_sh[TQ];

    const int t  = threadIdx.x;
    const int bh = blockIdx.y;
    const int q0 = blockIdx.x * TQ;
    const float scale = *scale_p;

    const int tx = t & 15;          // 16 col-groups of 4
    const int ty = t >> 4;          // 16 row-groups of 2
    const int r0 = 2*ty, r1 = r0 + 1;
    const int c0 = 4*tx;

    // ---- load Q tile (coalesced float4 -> padded smem) ----
    const float* qbase = q + ((size_t)bh * LL + q0) * DD;
    #pragma unroll
    for (int i = t; i < TQ*DD/4; i += 256) {
        float4 val = ((const float4*)qbase)[i];
        int row = i >> 4; int col = (i & 15) * 4;
        Qs[row][col+0] = val.x; Qs[row][col+1] = val.y;
        Qs[row][col+2] = val.z; Qs[row][col+3] = val.w;
    }
    if (t < TQ) l_sh[t] = 0.f;

    float o00=0,o01=0,o02=0,o03=0,o10=0,o11=0,o12=0,o13=0;
    float lp0 = 0.f, lp1 = 0.f;

    const float* kbh = k + (size_t)bh * LL * DD;
    const float* vbh = v + (size_t)bh * LL * DD;
    const int*  validb = valid + ((size_t)bh * LL + q0) * LL;
    float*      attwb  = attw  + ((size_t)bh * LL + q0) * LL;

    for (int kt = 0; kt < LL/TK; ++kt) {
        const int kb = kt * TK;
        __syncthreads();   // protect Ks/Es from previous iteration readers
        // ---- load K tile ----
        const float4* ksrc = (const float4*)(kbh + (size_t)kb * DD);
        #pragma unroll
        for (int i = t; i < TK*DD/4; i += 256) {
            float4 val = ksrc[i];
            int row = i >> 4; int col = (i & 15) * 4;
            Ks[row][col+0] = val.x; Ks[row][col+1] = val.y;
            Ks[row][col+2] = val.z; Ks[row][col+3] = val.w;
        }
        __syncthreads();

        // ---- S = Q * K^T  (2x4 micro-tile per thread) ----
        float a00=0,a01=0,a02=0,a03=0,a10=0,a11=0,a12=0,a13=0;
        #pragma unroll 8
        for (int d = 0; d < DD; ++d) {
            float qa = Qs[r0][d], qb = Qs[r1][d];
            float k0v = Ks[c0+0][d], k1v = Ks[c0+1][d];
            float k2v = Ks[c0+2][d], k3v = Ks[c0+3][d];
            a00 += qa*k0v; a01 += qa*k1v; a02 += qa*k2v; a03 += qa*k3v;
            a10 += qb*k0v; a11 += qb*k1v; a12 += qb*k2v; a13 += qb*k3v;
        }

        // ---- mask + exp (no max-shift needed) + write unnormalized attw + stage E ----
        {
            int4 m0 = *(const int4*)(validb + (size_t)r0 * LL + kb + c0);
            float4 e0;
            e0.x = (m0.x > 0) ? __expf(a00*scale) : 0.f;
            e0.y = (m0.y > 0) ? __expf(a01*scale) : 0.f;
            e0.z = (m0.z > 0) ? __expf(a02*scale) : 0.f;
            e0.w = (m0.w > 0) ? __expf(a03*scale) : 0.f;
            *(float4*)(attwb + (size_t)r0 * LL + kb + c0) = e0;
            lp0 += (e0.x + e0.y) + (e0.z + e0.w);
            Es[r0][c0+0] = e0.x; Es[r0][c0+1] = e0.y;
            Es[r0][c0+2] = e0.z; Es[r0][c0+3] = e0.w;

            int4 m1 = *(const int4*)(validb + (size_t)r1 * LL + kb + c0);
            float4 e1;
            e1.x = (m1.x > 0) ? __expf(a10*scale) : 0.f;
            e1.y = (m1.y > 0) ? __expf(a11*scale) : 0.f;
            e1.z = (m1.z > 0) ? __expf(a12*scale) : 0.f;
            e1.w = (m1.w > 0) ? __expf(a13*scale) : 0.f;
            *(float4*)(attwb + (size_t)r1 * LL + kb + c0) = e1;
            lp1 += (e1.x + e1.y) + (e1.z + e1.w);
            Es[r1][c0+0] = e1.x; Es[r1][c0+1] = e1.y;
            Es[r1][c0+2] = e1.z; Es[r1][c0+3] = e1.w;
        }
        __syncthreads();   // Ks (K) fully consumed, Es staged

        // ---- load V tile into Ks buffer ----
        const float4* vsrc = (const float4*)(vbh + (size_t)kb * DD);
        #pragma unroll
        for (int i = t; i < TK*DD/4; i += 256) {
            float4 val = vsrc[i];
            int row = i >> 4; int col = (i & 15) * 4;
            Ks[row][col+0] = val.x; Ks[row][col+1] = val.y;
            Ks[row][col+2] = val.z; Ks[row][col+3] = val.w;
        }
        __syncthreads();

        // ---- O += E * V ----
        #pragma unroll 8
        for (int c = 0; c < TK; ++c) {
            float ea = Es[r0][c], eb = Es[r1][c];
            float v0 = Ks[c][c0+0], v1 = Ks[c][c0+1];
            float v2 = Ks[c][c0+2], v3 = Ks[c][c0+3];
            o00 += ea*v0; o01 += ea*v1; o02 += ea*v2; o03 += ea*v3;
            o10 += eb*v0; o11 += eb*v1; o12 += eb*v2; o13 += eb*v3;
        }
    }

    // ---- reduce row sums, compute inverses, publish for fixup ----
    atomicAdd(&l_sh[r0], lp0);
    atomicAdd(&l_sh[r1], lp1);
    __syncthreads();
    if (t < TQ) {
        float l = l_sh[t];
        float inv = (l > 0.f) ? (1.0f / l) : 0.f;
        inv_sh[t] = inv;
        g_inv[bh * LL + q0 + t] = inv;
    }
    __syncthreads();

    // ---- write result (normalized) ----
    float inv0 = inv_sh[r0], inv1 = inv_sh[r1];
    float* rb = res + ((size_t)bh * LL + q0) * DD;
    float4 out0 = make_float4(o00*inv0, o01*inv0, o02*inv0, o03*inv0);
    float4 out1 = make_float4(o10*inv1, o11*inv1, o12*inv1, o13*inv1);
    *(float4*)(rb + (size_t)r0 * DD + c0) = out0;
    *(float4*)(rb + (size_t)r1 * DD + c0) = out1;
}

// scale att_w rows by 1/l (att_w was written unnormalized)
__global__ __launch_bounds__(256) void fixup_kernel(float* __restrict__ attw)
{
    size_t idx = (size_t)blockIdx.x * blockDim.x + threadIdx.x;   // float4 index
    // 2048 floats per row -> 512 float4 per row
    float inv = g_inv[idx >> 9];
    float4* p = (float4*)attw + idx;
    float4 val = *p;
    val.x *= inv; val.y *= inv; val.z *= inv; val.w *= inv;
    *p = val;
}

extern "C" void kernel_launch(void* const* d_in, const int* in_sizes, int n_in,
                              void* d_out, int out_size)
{
    const float* q     = (const float*)d_in[0];
    const float* k     = (const float*)d_in[1];
    const float* v     = (const float*)d_in[2];
    const int*   valid = (const int*)  d_in[3];
    const float* scale = (const float*)d_in[4];

    float* res  = (float*)d_out;                              // [B,H,L,D]
    float* attw = res + (size_t)NBH * LL * DD;                // [B,H,L,L]

    dim3 grid(LL / TQ, NBH);      // (64, 32)
    attn_kernel<<<grid, 256>>>(q, k, v, valid, scale, res, attw);

    // 134,217,728 floats / 4 = 33,554,432 float4 / 256 threads = 131072 blocks
    fixup_kernel<<<(NBH * (size_t)LL * LL / 4) / 256, 256>>>(attw);
}

// round 4
// speedup vs baseline: 3.2401x; 3.2401x over previous
#include <cuda_runtime.h>
#include <cuda_bf16.h>
#include <cstdint>

#define LL 2048
#define DD 64
#define NBH 32
#define TM 128
#define TN 64
#define NIT (LL/TN)    // 32
#define PSTR 72        // padded row stride in halves (144B: 16B-aligned, ldmatrix conflict-free)

// dynamic smem byte offsets
#define QHI_B 0u
#define QLO_B 18432u
#define KHI_B 36864u
#define KLO_B 46080u
#define VHI_B 55296u
#define VLO_B 64512u
#define PHI_B 73728u
#define PLO_B 92160u
#define RS_B  110592u
#define SM_TOTAL 111104u

__device__ float g_inv[NBH * LL];

__device__ __forceinline__ uint32_t smem_u32(const void* p){
    uint32_t a;
    asm("{ .reg .u64 t; cvta.to.shared.u64 t, %1; cvt.u32.u64 %0, t; }" : "=r"(a) : "l"(p));
    return a;
}
__device__ __forceinline__ void ldsm4(uint32_t* r, uint32_t a){
    asm volatile("ldmatrix.sync.aligned.m8n8.x4.shared.b16 {%0,%1,%2,%3}, [%4];"
        : "=r"(r[0]),"=r"(r[1]),"=r"(r[2]),"=r"(r[3]) : "r"(a));
}
__device__ __forceinline__ void ldsm4t(uint32_t* r, uint32_t a){
    asm volatile("ldmatrix.sync.aligned.m8n8.x4.trans.shared.b16 {%0,%1,%2,%3}, [%4];"
        : "=r"(r[0]),"=r"(r[1]),"=r"(r[2]),"=r"(r[3]) : "r"(a));
}
__device__ __forceinline__ void mma16816(float* c, const uint32_t* a, const uint32_t* b){
    asm volatile("mma.sync.aligned.m16n8k16.row.col.f32.bf16.bf16.f32 "
        "{%0,%1,%2,%3}, {%4,%5,%6,%7}, {%8,%9}, {%0,%1,%2,%3};"
        : "+f"(c[0]),"+f"(c[1]),"+f"(c[2]),"+f"(c[3])
        : "r"(a[0]),"r"(a[1]),"r"(a[2]),"r"(a[3]),"r"(b[0]),"r"(b[1]));
}
__device__ __forceinline__ uint32_t packbf(__nv_bfloat16 a, __nv_bfloat16 b){
    return ((uint32_t)__bfloat16_as_ushort(b)<<16)|(uint32_t)__bfloat16_as_ushort(a);
}
__device__ __forceinline__ void split2(float a, float b, uint32_t& hi, uint32_t& lo){
    __nv_bfloat16 ha=__float2bfloat16(a), hb=__float2bfloat16(b);
    hi = packbf(ha,hb);
    lo = packbf(__float2bfloat16(a-__bfloat162float(ha)),
                __float2bfloat16(b-__bfloat162float(hb)));
}
__device__ __forceinline__ void split_store(char* hi, char* lo, uint32_t off, float4 x){
    uint32_t h0,l0,h1,l1;
    split2(x.x,x.y,h0,l0); split2(x.z,x.w,h1,l1);
    *(uint2*)(hi+off) = make_uint2(h0,h1);
    *(uint2*)(lo+off) = make_uint2(l0,l1);
}

__global__ __launch_bounds__(256,2) void attn_mma(
    const float* __restrict__ q, const float* __restrict__ k,
    const float* __restrict__ v, const int* __restrict__ valid,
    const float* __restrict__ scale_p,
    float* __restrict__ res, float* __restrict__ attw)
{
    extern __shared__ char smem[];
    const uint32_t sb = smem_u32(smem);
    const int tid = threadIdx.x, w = tid>>5, l = tid&31;
    const int wm = w&3, wn = w>>2;        // 4 warps along M, 2 along N
    const int bh = blockIdx.y, q0 = blockIdx.x*TM;
    const float scale = *scale_p;
    float* rowsum = (float*)(smem + RS_B);
    if (tid < TM) rowsum[tid] = 0.f;

    // ---- Q load + bf16 hi/lo split ----
    const float4* qsrc = (const float4*)(q + ((size_t)bh*LL+q0)*DD);
    #pragma unroll
    for (int j=0;j<8;j++){
        int i = tid + j*256;
        int row = i>>4, c4 = (i&15)*4;
        split_store(smem+QHI_B, smem+QLO_B, (uint32_t)(row*PSTR+c4)*2u, qsrc[i]);
    }

    const float* kbh_ = k + (size_t)bh*LL*DD;
    const float* vbh_ = v + (size_t)bh*LL*DD;
    const int* validb = valid + ((size_t)bh*LL+q0)*LL;
    float* attwb = attw + ((size_t)bh*LL+q0)*LL;

    // ---- per-lane ldmatrix address bases ----
    const int arow = l&15, acolh = (l>>4)*8;  // A-operand lane mapping
    const int bg = l>>3, blr = l&7;           // B-operand lane mapping
    uint32_t qa[2], pa[2], kbA[2], vbA[2];
    #pragma unroll
    for (int m=0;m<2;m++){
        uint32_t ro = (uint32_t)((wm*32 + m*16 + arow)*PSTR + acolh)*2u;
        qa[m] = sb + QHI_B + ro;
        pa[m] = sb + PHI_B + ro;
    }
    #pragma unroll
    for (int p=0;p<2;p++){
        // K (B operand, non-trans): key rows, k=d cols
        kbA[p] = sb + KHI_B + (uint32_t)((wn*32 + p*16 + (bg>>1)*8 + blr)*PSTR + (bg&1)*8)*2u;
        // V (B operand, trans): key rows, d cols
        vbA[p] = sb + VHI_B + (uint32_t)(((bg&1)*8 + blr)*PSTR + wn*32 + p*16 + (bg>>1)*8)*2u;
    }

    float ofr[2][4][4];
    #pragma unroll
    for(int m=0;m<2;m++){
        #pragma unroll
        for(int n=0;n<4;n++){
            #pragma unroll
            for(int i=0;i<4;i++) ofr[m][n][i]=0.f;
        }
    }
    float lp[2][2] = {{0.f,0.f},{0.f,0.f}};

    #pragma unroll 1
    for (int it=0; it<NIT; ++it){
        const int kb = it*TN;
        __syncthreads();   // previous PV done: K/V/P buffers free
        // ---- K,V tile load + split ----
        const float4* ks_ = (const float4*)(kbh_ + (size_t)kb*DD);
        const float4* vs_ = (const float4*)(vbh_ + (size_t)kb*DD);
        #pragma unroll
        for (int j=0;j<4;j++){
            int i = tid + j*256;
            int row = i>>4, c4=(i&15)*4;
            uint32_t off = (uint32_t)(row*PSTR+c4)*2u;
            split_store(smem+KHI_B, smem+KLO_B, off, ks_[i]);
            split_store(smem+VHI_B, smem+VLO_B, off, vs_[i]);
        }
        __syncthreads();

        // ---- S = Q K^T, bf16x3 ----
        float sf[2][4][4];
        #pragma unroll
        for(int m=0;m<2;m++){
            #pragma unroll
            for(int n=0;n<4;n++){
                #pragma unroll
                for(int i=0;i<4;i++) sf[m][n][i]=0.f;
            }
        }

        #pragma unroll
        for (int ksI=0; ksI<4; ++ksI){
            uint32_t aH[2][4], aL[2][4], bH[2][4], bL[2][4];
            #pragma unroll
            for (int m=0;m<2;m++){
                ldsm4(aH[m], qa[m] + ksI*32);
                ldsm4(aL[m], qa[m] + (QLO_B-QHI_B) + ksI*32);
            }
            #pragma unroll
            for (int p=0;p<2;p++){
                ldsm4(bH[p], kbA[p] + ksI*32);
                ldsm4(bL[p], kbA[p] + (KLO_B-KHI_B) + ksI*32);
            }
            #pragma unroll
            for (int m=0;m<2;m++){
                #pragma unroll
                for (int n=0;n<4;n++){
                    const uint32_t* bh2 = &bH[n>>1][(n&1)*2];
                    const uint32_t* bl2 = &bL[n>>1][(n&1)*2];
                    mma16816(sf[m][n], aH[m], bh2);
                    mma16816(sf[m][n], aH[m], bl2);
                    mma16816(sf[m][n], aL[m], bh2);
                }
            }
        }

        // ---- epilogue: mask + exp + attw store + P split to smem ----
        #pragma unroll
        for (int m=0;m<2;m++){
            const int r0 = wm*32 + m*16 + (l>>2);
            #pragma unroll
            for (int n=0;n<4;n++){
                const int cl = wn*32 + n*8 + (l&3)*2;
                const int2 v0 = *(const int2*)(validb + (size_t)r0*LL + kb + cl);
                const int2 v1 = *(const int2*)(validb + (size_t)(r0+8)*LL + kb + cl);
                float e00 = v0.x>0 ? __expf(sf[m][n][0]*scale) : 0.f;
                float e01 = v0.y>0 ? __expf(sf[m][n][1]*scale) : 0.f;
                float e10 = v1.x>0 ? __expf(sf[m][n][2]*scale) : 0.f;
                float e11 = v1.y>0 ? __expf(sf[m][n][3]*scale) : 0.f;
                lp[m][0] += e00+e01; lp[m][1] += e10+e11;
                *(float2*)(attwb + (size_t)r0*LL + kb + cl)     = make_float2(e00,e01);
                *(float2*)(attwb + (size_t)(r0+8)*LL + kb + cl) = make_float2(e10,e11);
                uint32_t h_,lo_;
                split2(e00,e01,h_,lo_);
                uint32_t o0 = (uint32_t)(r0*PSTR + cl)*2u;
                *(uint32_t*)(smem+PHI_B+o0) = h_; *(uint32_t*)(smem+PLO_B+o0) = lo_;
                split2(e10,e11,h_,lo_);
                uint32_t o1 = (uint32_t)((r0+8)*PSTR + cl)*2u;
                *(uint32_t*)(smem+PHI_B+o1) = h_; *(uint32_t*)(smem+PLO_B+o1) = lo_;
            }
        }
        __syncthreads();   // P visible to all warps

        // ---- O += P V, bf16x3 (V via ldmatrix.trans) ----
        #pragma unroll
        for (int ksI=0;ksI<4;++ksI){
            uint32_t pH[2][4], pL[2][4], vH[2][4], vL[2][4];
            #pragma unroll
            for (int m=0;m<2;m++){
                ldsm4(pH[m], pa[m] + ksI*32);
                ldsm4(pL[m], pa[m] + (PLO_B-PHI_B) + ksI*32);
            }
            #pragma unroll
            for (int p=0;p<2;p++){
                ldsm4t(vH[p], vbA[p] + ksI*2304);   // 16 key rows * 144B
                ldsm4t(vL[p], vbA[p] + (VLO_B-VHI_B) + ksI*2304);
            }
            #pragma unroll
            for (int m=0;m<2;m++){
                #pragma unroll
                for (int n=0;n<4;n++){
                    const uint32_t* vh2 = &vH[n>>1][(n&1)*2];
                    const uint32_t* vl2 = &vL[n>>1][(n&1)*2];
                    mma16816(ofr[m][n], pH[m], vh2);
                    mma16816(ofr[m][n], pH[m], vl2);
                    mma16816(ofr[m][n], pL[m], vh2);
                }
            }
        }
    }

    // ---- row-sum reduction -> inverse ----
    #pragma unroll
    for (int m=0;m<2;m++){
        #pragma unroll
        for (int h=0;h<2;h++){
            float x = lp[m][h];
            x += __shfl_xor_sync(0xffffffffu, x, 1);
            x += __shfl_xor_sync(0xffffffffu, x, 2);
            if ((l&3)==0) atomicAdd(&rowsum[wm*32 + m*16 + h*8 + (l>>2)], x);
        }
    }
    __syncthreads();
    if (tid < TM){
        float s_ = rowsum[tid];
        float inv = s_>0.f ? 1.f/s_ : 0.f;
        g_inv[bh*LL + q0 + tid] = inv;
        rowsum[tid] = inv;
    }
    __syncthreads();

    // ---- normalized result write ----
    float* resb = res + ((size_t)bh*LL+q0)*DD;
    #pragma unroll
    for (int m=0;m<2;m++){
        const int r0 = wm*32 + m*16 + (l>>2);
        float i0 = rowsum[r0], i1 = rowsum[r0+8];
        #pragma unroll
        for (int n=0;n<4;n++){
            const int dc = wn*32 + n*8 + (l&3)*2;
            *(float2*)(resb + (size_t)r0*DD + dc)     = make_float2(ofr[m][n][0]*i0, ofr[m][n][1]*i0);
            *(float2*)(resb + (size_t)(r0+8)*DD + dc) = make_float2(ofr[m][n][2]*i1, ofr[m][n][3]*i1);
        }
    }
}

// scale att_w rows by 1/l (att_w was written unnormalized)
__global__ __launch_bounds__(256) void fixup_kernel(float* __restrict__ attw)
{
    size_t idx = (size_t)blockIdx.x * blockDim.x + threadIdx.x;   // float4 index
    float inv = g_inv[idx >> 9];
    float4* p = (float4*)attw + idx;
    float4 val = *p;
    val.x *= inv; val.y *= inv; val.z *= inv; val.w *= inv;
    *p = val;
}

extern "C" void kernel_launch(void* const* d_in, const int* in_sizes, int n_in,
                              void* d_out, int out_size)
{
    const float* q     = (const float*)d_in[0];
    const float* k     = (const float*)d_in[1];
    const float* v     = (const float*)d_in[2];
    const int*   valid = (const int*)  d_in[3];
    const float* scale = (const float*)d_in[4];

    float* res  = (float*)d_out;                      // [B,H,L,D]
    float* attw = res + (size_t)NBH * LL * DD;        // [B,H,L,L]

    cudaFuncSetAttribute(attn_mma, cudaFuncAttributeMaxDynamicSharedMemorySize, SM_TOTAL);

    dim3 grid(LL / TM, NBH);   // (16, 32)
    attn_mma<<<grid, 256, SM_TOTAL>>>(q, k, v, valid, scale, res, attw);

    fixup_kernel<<<(NBH * (size_t)LL * LL / 4) / 256, 256>>>(attw);
}